// round 15
// baseline (speedup 1.0000x reference)
#include <cuda_runtime.h>
#include <cuda_bf16.h>

// SparseToDense via inverse-gather, channel-major write sweeps.
//   1) memset node: g_inv[:] = -1
//   2) build: atomicExch head insert + chain link
//   3) gather_cmaj: grid (spatial, C/4). Resident blocks share one channel
//      chunk -> the chip streams 4 contiguous output planes linearly
//      (memset-like DRAM behavior). g_inv + feats are L2-resident after the
//      first chunk wave. Thread owns 4 cells: int4 head load, 16B feature
//      loads for active cells, 4x4 register transpose, 4 coalesced STG.128.

#define NTHREADS 256
#define CPT 4                    // cells per thread
#define CELLS_PER_BLOCK (NTHREADS * CPT)   // 1024 (divides S3)
#define MAX_BS3 (4 * 1024 * 1024)
#define MAX_N   (4 * 1024 * 1024)
#define C64 64

__device__ __align__(16) int g_inv[MAX_BS3];
__device__ int g_next[MAX_N];

__global__ void build_inv(const int* __restrict__ idx, int N, int BS3) {
    int n = blockIdx.x * blockDim.x + threadIdx.x;
    if (n >= N) return;
    int r = idx[n];
    if ((unsigned)r >= (unsigned)BS3) return;       // defensive
    int old = atomicExch(&g_inv[r], n);             // push-front
    g_next[n] = old;                                // coalesced chain link
}

__global__ __launch_bounds__(NTHREADS, 8)
void gather_cmaj(const float* __restrict__ feats,
                 const int* __restrict__ s_ptr,
                 float* __restrict__ out, int BS3) {
    const int S  = s_ptr[0];
    const int S3 = S * S * S;
    const int c0 = blockIdx.y << 2;                 // this block's 4 channels

    const int base = blockIdx.x * CELLS_PER_BLOCK + threadIdx.x * CPT;

    if (base + CPT <= BS3) {
        // Heads of this thread's 4 cells: one coalesced LDG.128 (L2-hot).
        int4 h = *reinterpret_cast<const int4*>(&g_inv[base]);

        float acc[CPT][4];
        #pragma unroll
        for (int e = 0; e < CPT; e++)
            acc[e][0] = acc[e][1] = acc[e][2] = acc[e][3] = 0.0f;

        if ((h.x | h.y | h.z | h.w) >= 0 ||
            (h.x >= 0) | (h.y >= 0) | (h.z >= 0) | (h.w >= 0)) {
            int heads[CPT] = {h.x, h.y, h.z, h.w};
            #pragma unroll
            for (int e = 0; e < CPT; e++) {
                int n = heads[e];
                while (n >= 0) {                     // chain length 1 for ~99%
                    float4 f = *reinterpret_cast<const float4*>(
                        feats + (long long)n * C64 + c0);   // 16B, L2-hot
                    acc[e][0] += f.x;
                    acc[e][1] += f.y;
                    acc[e][2] += f.z;
                    acc[e][3] += f.w;
                    n = g_next[n];
                }
            }
        }

        // Quad never straddles a batch (S3 % CELLS_PER_BLOCK == 0).
        const int b  = base / S3;
        const int sp = base - b * S3;
        const long long s3 = S3;
        float* o = out + ((long long)b * C64 + c0) * s3 + sp;

        // 4x4 register transpose -> 4 coalesced STG.128 (512B/warp/channel,
        // 4KB/block/channel, linear across blocks).
        #pragma unroll
        for (int j = 0; j < 4; j++) {
            float4 v = make_float4(acc[0][j], acc[1][j], acc[2][j], acc[3][j]);
            __stcs(reinterpret_cast<float4*>(o + (long long)j * s3), v);
        }
    } else {
        // Tail fallback (unused when BS3 % CELLS_PER_BLOCK == 0).
        const long long s3 = S3;
        for (int e = 0; e < CPT; e++) {
            int g = base + e;
            if (g >= BS3) break;
            int b = g / S3, sp = g - b * S3;
            int n0 = g_inv[g];
            for (int j = 0; j < 4; j++) {
                float a = 0.0f;
                int n = n0;
                while (n >= 0) {
                    a += feats[(long long)n * C64 + c0 + j];
                    n = g_next[n];
                }
                out[((long long)b * C64 + c0 + j) * s3 + sp] = a;
            }
        }
    }
}

extern "C" void kernel_launch(void* const* d_in, const int* in_sizes, int n_in,
                              void* d_out, int out_size) {
    const float* feats = (const float*)d_in[0];
    const int*   idx   = (const int*)d_in[1];
    const int*   s_ptr = (const int*)d_in[2];
    float*       out   = (float*)d_out;

    const int N   = in_sizes[1];           // 262144 active sites
    const int BS3 = out_size / C64;        // B * S^3 = 2M

    void* inv_ptr = nullptr;
    cudaGetSymbolAddress(&inv_ptr, g_inv);
    cudaMemsetAsync(inv_ptr, 0xFF, (size_t)BS3 * sizeof(int), 0);

    build_inv<<<(N + 255) / 256, 256>>>(idx, N, BS3);

    dim3 grid((BS3 + CELLS_PER_BLOCK - 1) / CELLS_PER_BLOCK, C64 / 4);
    gather_cmaj<<<grid, NTHREADS>>>(feats, s_ptr, out, BS3);
}

// round 16
// speedup vs baseline: 1.0728x; 1.0728x over previous
#include <cuda_runtime.h>
#include <cuda_bf16.h>

// SparseToDense via inverse-gather, persistent warp-autonomous register path.
//   1) memset node: g_inv[:] = -1
//   2) build: atomicExch head insert + chain link
//   3) gather_persist: grid == resident CTAs (888). Each WARP independently
//      processes 128-cell tiles at stride total_warps (round-robin). Lane
//      owns 4 consecutive cells: one coalesced int4 head load, chain-summed
//      16B feature loads per 4-channel chunk, 4x4 register transpose,
//      4 coalesced STG.128 per chunk. No SMEM, no barriers, no shared
//      atomics -- loads and stores stay mixed for maximal MLP; per-SM work
//      is uniform so there is no wave-quantization tail.

#define NTHREADS 256
#define CPB 6                    // CTAs per SM
#define CPT 4                    // cells per thread (one quad)
#define WTILE (32 * CPT)         // cells per warp-tile = 128
#define MAX_BS3 (4 * 1024 * 1024)
#define MAX_N   (4 * 1024 * 1024)
#define C64 64

__device__ __align__(16) int g_inv[MAX_BS3];
__device__ int g_next[MAX_N];

__global__ void build_inv(const int* __restrict__ idx, int N, int BS3) {
    int n = blockIdx.x * blockDim.x + threadIdx.x;
    if (n >= N) return;
    int r = idx[n];
    if ((unsigned)r >= (unsigned)BS3) return;       // defensive
    int old = atomicExch(&g_inv[r], n);             // push-front
    g_next[n] = old;                                // coalesced chain link
}

__global__ __launch_bounds__(NTHREADS, CPB)
void gather_persist(const float* __restrict__ feats,
                    const int* __restrict__ s_ptr,
                    float* __restrict__ out, int BS3) {
    const int S  = s_ptr[0];
    const int S3 = S * S * S;

    const int lane = threadIdx.x & 31;
    const int gw   = blockIdx.x * (NTHREADS >> 5) + (threadIdx.x >> 5);
    const int nw   = gridDim.x * (NTHREADS >> 5);   // total warps
    const int ntiles = (BS3 + WTILE - 1) / WTILE;

    for (int t = gw; t < ntiles; t += nw) {
        const int base = t * WTILE + lane * CPT;

        if (base + CPT <= BS3) {
            // Heads of this lane's 4 cells: one coalesced LDG.128.
            int4 h = *reinterpret_cast<const int4*>(&g_inv[base]);
            const bool any = (h.x >= 0) | (h.y >= 0) | (h.z >= 0) | (h.w >= 0);
            int heads[CPT] = {h.x, h.y, h.z, h.w};

            // Quad never straddles a batch (S3 % WTILE == 0 in practice).
            const int b  = base / S3;
            const int sp = base - b * S3;
            const long long s3 = S3;
            float* o = out + (long long)b * C64 * s3 + sp;

            #pragma unroll
            for (int c0 = 0; c0 < C64; c0 += 4) {
                float acc[CPT][4];
                #pragma unroll
                for (int e = 0; e < CPT; e++)
                    acc[e][0] = acc[e][1] = acc[e][2] = acc[e][3] = 0.0f;

                if (any) {
                    #pragma unroll
                    for (int e = 0; e < CPT; e++) {
                        int n = heads[e];
                        while (n >= 0) {             // chain length 1 for ~99%
                            float4 f = *reinterpret_cast<const float4*>(
                                feats + (long long)n * C64 + c0);
                            acc[e][0] += f.x;
                            acc[e][1] += f.y;
                            acc[e][2] += f.z;
                            acc[e][3] += f.w;
                            n = g_next[n];
                        }
                    }
                }
                // 4x4 register transpose -> 4 coalesced STG.128.
                #pragma unroll
                for (int j = 0; j < 4; j++) {
                    float4 v = make_float4(acc[0][j], acc[1][j],
                                           acc[2][j], acc[3][j]);
                    __stcs(reinterpret_cast<float4*>(
                               o + (long long)(c0 + j) * s3), v);
                }
            }
        } else {
            // Tail fallback (unused when BS3 % WTILE == 0).
            const long long s3 = S3;
            for (int e = 0; e < CPT; e++) {
                int g = base + e;
                if (g >= BS3) break;
                int b = g / S3, sp = g - b * S3;
                int n0 = g_inv[g];
                for (int c = 0; c < C64; c++) {
                    float a = 0.0f;
                    int n = n0;
                    while (n >= 0) {
                        a += feats[(long long)n * C64 + c];
                        n = g_next[n];
                    }
                    out[((long long)b * C64 + c) * s3 + sp] = a;
                }
            }
        }
    }
}

extern "C" void kernel_launch(void* const* d_in, const int* in_sizes, int n_in,
                              void* d_out, int out_size) {
    const float* feats = (const float*)d_in[0];
    const int*   idx   = (const int*)d_in[1];
    const int*   s_ptr = (const int*)d_in[2];
    float*       out   = (float*)d_out;

    const int N   = in_sizes[1];           // 262144 active sites
    const int BS3 = out_size / C64;        // B * S^3 = 2M

    void* inv_ptr = nullptr;
    cudaGetSymbolAddress(&inv_ptr, g_inv);
    cudaMemsetAsync(inv_ptr, 0xFF, (size_t)BS3 * sizeof(int), 0);

    build_inv<<<(N + 255) / 256, 256>>>(idx, N, BS3);

    int ntiles = (BS3 + WTILE - 1) / WTILE;
    int blocks = 148 * CPB;                // persistent: one wave exactly
    int maxb   = (ntiles + (NTHREADS >> 5) - 1) / (NTHREADS >> 5);
    if (blocks > maxb) blocks = maxb;
    gather_persist<<<blocks, NTHREADS>>>(feats, s_ptr, out, BS3);
}

// round 17
// speedup vs baseline: 1.1822x; 1.1020x over previous
#include <cuda_runtime.h>
#include <cuda_bf16.h>

// SparseToDense via inverse-gather with collision chains (R6 structure,
// self-cleaning table + ballot compaction).
//   1) build: atomicExch head insert (stores n+1; 0 = empty), chain link
//   2) gather: per 128-cell tile:
//        - warp 0 loads the 128 heads as int4, WRITES ZEROS BACK (the table
//          is all-zero at kernel exit == its static initial state, so no
//          memset is ever needed), builds the 4 element-ballot masks and the
//          compacted (sp, n) list via shfl prefix scan. No shared atomics.
//        - fill: warp-per-cell chain-summed coalesced 256B feature rows into
//          the quad-rotated 32KB tile.
//        - drain: ballot-masked float4 selects + coalesced STG.128.
//
// SMEM tile layout: tile[c][pq][e], pq = ((sp>>2) + c) & 31, e = sp & 3.
// Drain reads physical quad = lane (linear LDS.128, conflict-free); rotation
// folds into the STG address (quad permutation within each 512B segment).

#define TILE 128
#define NTHREADS 256
#define MAX_BS3 (4 * 1024 * 1024)
#define MAX_N   (4 * 1024 * 1024)
#define C64 64

__device__ __align__(16) int g_inv[MAX_BS3];   // zero-init; kernel restores
__device__ int g_next[MAX_N];

__global__ void build_inv(const int* __restrict__ idx, int N, int BS3) {
    int n = blockIdx.x * blockDim.x + threadIdx.x;
    if (n >= N) return;
    int r = idx[n];
    if ((unsigned)r >= (unsigned)BS3) return;       // defensive
    int old = atomicExch(&g_inv[r], n + 1);         // push-front, 0 = empty
    g_next[n] = old - 1;                            // -1 = end of chain
}

__global__ __launch_bounds__(NTHREADS, 6)
void gather_write(const float* __restrict__ feats,
                  const int* __restrict__ s_ptr,
                  float* __restrict__ out, int BS3) {
    __shared__ float tile[C64 * TILE];   // 32 KB, quad-rotated
    __shared__ int list_sp[TILE];
    __shared__ int list_n[TILE];
    __shared__ unsigned embal[4];        // element ballots: x,y,z,w over quads
    __shared__ int lcnt;

    const int S  = s_ptr[0];
    const int S3 = S * S * S;
    const int tid  = threadIdx.x;
    const int lane = tid & 31;
    const int wid  = tid >> 5;            // 0..7
    const int g0   = blockIdx.x * TILE;
    const bool full = (g0 + TILE <= BS3);

    // Warp 0: read heads (int4/lane), reset table, compact via ballots.
    if (wid == 0) {
        int4 q = make_int4(0, 0, 0, 0);
        const int g = g0 + 4 * lane;
        if (full || g + 3 < BS3) {
            q = *reinterpret_cast<const int4*>(&g_inv[g]);
            if (q.x | q.y | q.z | q.w)              // restore zeros (self-clean)
                *reinterpret_cast<int4*>(&g_inv[g]) = make_int4(0, 0, 0, 0);
        }
        unsigned bx = __ballot_sync(0xffffffffu, q.x != 0);
        unsigned by = __ballot_sync(0xffffffffu, q.y != 0);
        unsigned bz = __ballot_sync(0xffffffffu, q.z != 0);
        unsigned bw = __ballot_sync(0xffffffffu, q.w != 0);
        int cnt = (q.x != 0) + (q.y != 0) + (q.z != 0) + (q.w != 0);
        int pre = cnt;                               // inclusive scan
        #pragma unroll
        for (int d = 1; d < 32; d <<= 1) {
            int v = __shfl_up_sync(0xffffffffu, pre, d);
            if (lane >= d) pre += v;
        }
        int pos = pre - cnt;                         // exclusive prefix
        int sp = 4 * lane;
        if (q.x) { list_sp[pos] = sp;     list_n[pos] = q.x - 1; pos++; }
        if (q.y) { list_sp[pos] = sp + 1; list_n[pos] = q.y - 1; pos++; }
        if (q.z) { list_sp[pos] = sp + 2; list_n[pos] = q.z - 1; pos++; }
        if (q.w) { list_sp[pos] = sp + 3; list_n[pos] = q.w - 1; pos++; }
        if (lane == 31) lcnt = pre;
        if (lane == 0) { embal[0] = bx; embal[1] = by; embal[2] = bz; embal[3] = bw; }
    }
    __syncthreads();

    // Fill: warp-per-cell coalesced feature fetch, chain-summed.
    for (int i = wid; i < lcnt; i += (NTHREADS >> 5)) {
        int sp = list_sp[i];
        int n  = list_n[i];
        float a0 = 0.0f, a1 = 0.0f;
        while (n >= 0) {                             // length 1 for ~99%
            const float* row = feats + (long long)n * C64;
            a0 += row[lane];
            a1 += row[lane + 32];
            n = g_next[n];                           // warp-uniform load
        }
        int sp4 = sp >> 2, e = sp & 3;
        int pq = (sp4 + lane) & 31;                  // same rotation both halves
        tile[lane * TILE + pq * 4 + e]        = a0;
        tile[(lane + 32) * TILE + pq * 4 + e] = a1;
    }
    __syncthreads();

    // Hoist ballots into registers.
    const unsigned mx = embal[0], my = embal[1], mz = embal[2], mw = embal[3];
    const unsigned many = mx | my | mz | mw;

    // Drain: warp owns 8 channels; lane reads physical quad `lane`.
    if (full) {
        const int b = g0 / S3;                      // TILE divides S3
        const long long s3 = S3;
        float* obase = out + (long long)b * C64 * s3 + (g0 - (long long)b * s3);
        const float4* trow = reinterpret_cast<const float4*>(tile);
        #pragma unroll
        for (int i = 0; i < 8; i++) {
            int c  = wid * 8 + i;
            int lq = (lane - c) & 31;                // logical quad
            float4 v = make_float4(0.f, 0.f, 0.f, 0.f);
            if ((many >> lq) & 1u) {
                float4 t = trow[c * (TILE / 4) + lane];   // linear, no conflict
                v.x = ((mx >> lq) & 1u) ? t.x : 0.f;
                v.y = ((my >> lq) & 1u) ? t.y : 0.f;
                v.z = ((mz >> lq) & 1u) ? t.z : 0.f;
                v.w = ((mw >> lq) & 1u) ? t.w : 0.f;
            }
            __stcs(reinterpret_cast<float4*>(obase + c * s3) + lq, v);
        }
    } else {
        // Tail fallback (unused when BS3 % TILE == 0): scalar masked writes.
        const long long s3 = S3;
        for (int sp = tid; sp < TILE; sp += NTHREADS) {
            int g = g0 + sp;
            if (g >= BS3) break;
            int b = g / S3, loc = g - b * S3;
            int lq = sp >> 2, e = sp & 3;
            unsigned mm = (e == 0) ? mx : (e == 1) ? my : (e == 2) ? mz : mw;
            bool act = (mm >> lq) & 1u;
            for (int c = 0; c < C64; c++) {
                int pq = (lq + c) & 31;
                out[(long long)b * C64 * s3 + (long long)c * s3 + loc] =
                    act ? tile[c * TILE + pq * 4 + e] : 0.f;
            }
        }
    }
}

extern "C" void kernel_launch(void* const* d_in, const int* in_sizes, int n_in,
                              void* d_out, int out_size) {
    const float* feats = (const float*)d_in[0];
    const int*   idx   = (const int*)d_in[1];
    const int*   s_ptr = (const int*)d_in[2];
    float*       out   = (float*)d_out;

    const int N   = in_sizes[1];           // 262144 active sites
    const int BS3 = out_size / C64;        // B * S^3 = 2M

    // No memset: g_inv is statically zero and gather_write restores zeros
    // behind itself every run (self-cleaning).
    build_inv<<<(N + 255) / 256, 256>>>(idx, N, BS3);
    gather_write<<<(BS3 + TILE - 1) / TILE, NTHREADS>>>(feats, s_ptr, out, BS3);
}